// round 16
// baseline (speedup 1.0000x reference)
#include <cuda_runtime.h>
#include <cuda_fp16.h>
#include <cstdint>

#define BB 4
#define SS 2048
#define EE 1024
#define HH 16
#define DD 64
#define QSC 0.18033688011112042f   // 0.125 * log2(e), folded into Q

// Scratch (fp16)
__device__ __half g_k[(size_t)BB*HH*SS*DD];    // [B][H][S][D]
__device__ __half g_vT[(size_t)BB*HH*DD*SS];   // [B][H][D][S] (pre-transposed)
__device__ __half g_att[(size_t)BB*SS*EE];     // FRAGMENT layout: uint4[tile_r][tile_k][lane]
__device__ __half g_wo[(size_t)EE*EE];         // fp16 copy of Wo

#define H2U(x) (*(const uint32_t*)&(x))

__device__ __forceinline__ uint32_t f2h2(float a, float b) {
    __half2 h = __floats2half2_rn(a, b);
    return H2U(h);
}
__device__ __forceinline__ float ex2f(float x) {   // single MUFU op
    float r;
    asm("ex2.approx.f32 %0, %1;" : "=f"(r) : "f"(x));
    return r;
}
__device__ __forceinline__ uint32_t smem_u32(const void* p) {
    return (uint32_t)__cvta_generic_to_shared(p);
}
__device__ __forceinline__ void ldm_x4(uint32_t* r, uint32_t a) {
    asm volatile("ldmatrix.sync.aligned.m8n8.x4.shared.b16 {%0,%1,%2,%3}, [%4];"
        : "=r"(r[0]), "=r"(r[1]), "=r"(r[2]), "=r"(r[3]) : "r"(a));
}
__device__ __forceinline__ void cp16(uint32_t dst, const void* src) {
    asm volatile("cp.async.cg.shared.global [%0], [%1], 16;" :: "r"(dst), "l"(src));
}
#define CPCOMMIT() asm volatile("cp.async.commit_group;" ::: "memory")
#define CPWAIT0()  asm volatile("cp.async.wait_group 0;" ::: "memory")
#define CPWAIT1()  asm volatile("cp.async.wait_group 1;" ::: "memory")

// D += A(m16k16 row) * B(n8k16 col), fp16 in / fp32 acc
__device__ __forceinline__ void mma16(float c[4], const uint32_t a[4], const uint32_t b[2]) {
    asm volatile("mma.sync.aligned.m16n8k16.row.col.f32.f16.f16.f32 "
        "{%0,%1,%2,%3}, {%4,%5,%6,%7}, {%8,%9}, {%0,%1,%2,%3};"
        : "+f"(c[0]), "+f"(c[1]), "+f"(c[2]), "+f"(c[3])
        : "r"(a[0]), "r"(a[1]), "r"(a[2]), "r"(a[3]), "r"(b[0]), "r"(b[1]));
}

// ======================= Kernel 0: Wo -> fp16 =======================
__global__ void __launch_bounds__(256) conv_wo(const float* __restrict__ Wo) {
    int i = (blockIdx.x * 256 + threadIdx.x) * 4;
    float4 v = *(const float4*)(Wo + i);
    *(uint2*)&g_wo[i] = make_uint2(f2h2(v.x, v.y), f2h2(v.z, v.w));
}

// ======================= Kernel A: K/V projections, 2 heads/CTA =======================
// smem halves: X0[128][72] | X1[128][72] | W[2][2][64][72]
#define HX0 0
#define HX1 9216
#define HWX 18432
#define QK_SZ ((18432 + 4*4608) * 2)

__global__ void __launch_bounds__(256, 1) kv_kernel(
    const float* __restrict__ x,
    const float* __restrict__ Wk, const float* __restrict__ Wv,
    const float* __restrict__ bk, const float* __restrict__ bv)
{
    extern __shared__ __half hs[];
    int tid = threadIdx.x, lane = tid & 31, wid = tid >> 5;
    int g = lane >> 2, t = lane & 3;
    int l8 = lane & 7, qd = lane >> 3;
    int a_m = ((qd & 1) << 3) + l8, a_k = (qd >> 1) << 3;
    int b_n = ((qd >> 1) << 3) + l8, b_k = (qd & 1) << 3;
    int wm = wid & 3, wn = wid >> 2;
    int hp = blockIdx.y;               // head pair
    int t0 = blockIdx.x * 128;
    int b = t0 >> 11, s0 = t0 & (SS - 1);
    uint32_t sb = smem_u32(hs);

#pragma unroll
    for (int i = 0; i < 8; i++) {
        int lin = tid + i * 256; int r = lin >> 4, c = (lin & 15) << 2;
        float4 v0 = *(const float4*)(x + (size_t)(t0 + r) * EE + (hp*2) * DD + c);
        *(uint2*)&hs[HX0 + r*72 + c] = make_uint2(f2h2(v0.x, v0.y), f2h2(v0.z, v0.w));
        float4 v1 = *(const float4*)(x + (size_t)(t0 + r) * EE + (hp*2+1) * DD + c);
        *(uint2*)&hs[HX1 + r*72 + c] = make_uint2(f2h2(v1.x, v1.y), f2h2(v1.z, v1.w));
    }
#pragma unroll
    for (int hi = 0; hi < 2; hi++) {
        const float* Wsrc[2] = {Wk + (size_t)(hp*2+hi)*DD*DD,
                                Wv + (size_t)(hp*2+hi)*DD*DD};
#pragma unroll
        for (int w = 0; w < 2; w++) {
            __half* Wd = hs + HWX + (hi*2 + w) * 4608;
#pragma unroll
            for (int i = 0; i < 4; i++) {
                int lin = tid + i * 256; int d = lin >> 4, e = (lin & 15) << 2;
                float4 v = *(const float4*)(Wsrc[w] + d * DD + e);
                Wd[(e+0)*72 + d] = __float2half_rn(v.x);
                Wd[(e+1)*72 + d] = __float2half_rn(v.y);
                Wd[(e+2)*72 + d] = __float2half_rn(v.z);
                Wd[(e+3)*72 + d] = __float2half_rn(v.w);
            }
        }
    }
    __syncthreads();

    for (int hi = 0; hi < 2; hi++) {
        int h = hp*2 + hi;
        int HX = hi ? HX1 : HX0;
        float c[2][2][4][4] = {};
#pragma unroll
        for (int kk = 0; kk < 4; kk++) {
            uint32_t af[2][4];
#pragma unroll
            for (int mi = 0; mi < 2; mi++)
                ldm_x4(af[mi], sb + (uint32_t)(HX + (wm*32 + mi*16 + a_m)*72 + kk*16 + a_k)*2);
#pragma unroll
            for (int w = 0; w < 2; w++) {
#pragma unroll
                for (int pr = 0; pr < 2; pr++) {
                    uint32_t bf[4];
                    ldm_x4(bf, sb + (uint32_t)(HWX + (hi*2+w)*4608 + (wn*32 + pr*16 + b_n)*72 + kk*16 + b_k)*2);
                    mma16(c[w][0][2*pr  ], af[0], bf);
                    mma16(c[w][0][2*pr+1], af[0], bf + 2);
                    mma16(c[w][1][2*pr  ], af[1], bf);
                    mma16(c[w][1][2*pr+1], af[1], bf + 2);
                }
            }
        }
        size_t base = (size_t)(b * HH + h) * SS * DD;
        // K store
#pragma unroll
        for (int ni = 0; ni < 4; ni++) {
            int e = wn*32 + ni*8 + 2*t;
            float2 bb2 = *(const float2*)(bk + h*DD + e);
#pragma unroll
            for (int mi = 0; mi < 2; mi++) {
                int r = wm*32 + mi*16 + g;
                *(uint32_t*)(g_k + base + (size_t)(s0 + r    )*DD + e) =
                    f2h2(c[0][mi][ni][0] + bb2.x, c[0][mi][ni][1] + bb2.y);
                *(uint32_t*)(g_k + base + (size_t)(s0 + r + 8)*DD + e) =
                    f2h2(c[0][mi][ni][2] + bb2.x, c[0][mi][ni][3] + bb2.y);
            }
        }
        // V store (transposed [d][s])
        size_t vbase = (size_t)(b * HH + h) * DD * SS;
#pragma unroll
        for (int ni = 0; ni < 4; ni++) {
            int e = wn*32 + ni*8 + 2*t;
            float2 bb2 = *(const float2*)(bv + h*DD + e);
#pragma unroll
            for (int mi = 0; mi < 2; mi++) {
                int r = wm*32 + mi*16 + g;
                g_vT[vbase + (size_t)(e  )*SS + s0 + r    ] = __float2half_rn(c[1][mi][ni][0] + bb2.x);
                g_vT[vbase + (size_t)(e+1)*SS + s0 + r    ] = __float2half_rn(c[1][mi][ni][1] + bb2.y);
                g_vT[vbase + (size_t)(e  )*SS + s0 + r + 8] = __float2half_rn(c[1][mi][ni][2] + bb2.x);
                g_vT[vbase + (size_t)(e+1)*SS + s0 + r + 8] = __float2half_rn(c[1][mi][ni][3] + bb2.y);
            }
        }
    }
}

// ======================= Kernel B: flash attention (R11 loop + inline Q projection) =======================
#define HQ  0
#define HK0 9216
#define HK1 13824
#define HV0 18432
#define HV1 23040
#define FST 13824              // float index of stage
#define FL  22528              // float index of l[2][128]
#define ASZ ((22528 + 256) * 4)
#define NIT (SS/64)

__global__ void __launch_bounds__(256, 1) attn_kernel(
    const float* __restrict__ x, const float* __restrict__ Wq, const float* __restrict__ bq)
{
    extern __shared__ __half hs[];
    float* sf = (float*)hs;
    int tid = threadIdx.x, lane = tid & 31, wid = tid >> 5;
    int g = lane >> 2, t = lane & 3;
    int l8 = lane & 7, qd = lane >> 3;
    int a_m = ((qd & 1) << 3) + l8, a_k = (qd >> 1) << 3;
    int b_n = ((qd >> 1) << 3) + l8, b_k = (qd & 1) << 3;
    int wm = wid & 3, wn = wid >> 2;
    int qt = blockIdx.x, h = blockIdx.y, b = blockIdx.z;
    size_t bh  = (size_t)(b * HH + h) * SS * DD;
    size_t bhv = (size_t)(b * HH + h) * DD * SS;
    const __half* kg = g_k + bh;
    const __half* vg = g_vT + bhv;
    uint32_t sb = smem_u32(hs);

    // ---- Q projection prologue: X -> HQ, Wq^T -> HK0 (temp), GEMM, Q -> HQ ----
    const float* xg = x + (size_t)(b * SS + qt * 128) * EE + h * DD;
#pragma unroll
    for (int i = 0; i < 8; i++) {
        int lin = tid + i * 256; int r = lin >> 4, c = (lin & 15) << 2;
        float4 v = *(const float4*)(xg + (size_t)r * EE + c);
        *(uint2*)&hs[HQ + r*72 + c] = make_uint2(f2h2(v.x, v.y), f2h2(v.z, v.w));
    }
    {
        const float* wqg = Wq + (size_t)h * DD * DD;
#pragma unroll
        for (int i = 0; i < 4; i++) {
            int lin = tid + i * 256; int d = lin >> 4, e = (lin & 15) << 2;
            float4 v = *(const float4*)(wqg + d * DD + e);
            hs[HK0 + (e+0)*72 + d] = __float2half_rn(v.x);
            hs[HK0 + (e+1)*72 + d] = __float2half_rn(v.y);
            hs[HK0 + (e+2)*72 + d] = __float2half_rn(v.z);
            hs[HK0 + (e+3)*72 + d] = __float2half_rn(v.w);
        }
    }
    __syncthreads();
    {
        float qc[2][8][4] = {};
#pragma unroll
        for (int kk = 0; kk < 4; kk++) {
            uint32_t af[2][4];
            ldm_x4(af[0], sb + (uint32_t)(HQ + (wm*32      + a_m)*72 + kk*16 + a_k)*2);
            ldm_x4(af[1], sb + (uint32_t)(HQ + (wm*32 + 16 + a_m)*72 + kk*16 + a_k)*2);
#pragma unroll
            for (int pr = 0; pr < 4; pr++) {
                uint32_t bf[4];
                ldm_x4(bf, sb + (uint32_t)(HK0 + (pr*16 + b_n)*72 + kk*16 + b_k)*2);
                mma16(qc[0][2*pr  ], af[0], bf);
                mma16(qc[0][2*pr+1], af[0], bf + 2);
                mma16(qc[1][2*pr  ], af[1], bf);
                mma16(qc[1][2*pr+1], af[1], bf + 2);
            }
        }
        __syncthreads();   // all X/W reads done; HQ and HK0 free for overwrite
        if (wn == 0) {
#pragma unroll
            for (int mi = 0; mi < 2; mi++)
#pragma unroll
            for (int ni = 0; ni < 8; ni++) {
                int e = ni*8 + 2*t;
                float2 bb = *(const float2*)(bq + h*DD + e);
                int r = wm*32 + mi*16 + g;
                *(uint32_t*)&hs[HQ + r*72 + e] =
                    f2h2((qc[mi][ni][0] + bb.x) * QSC, (qc[mi][ni][1] + bb.y) * QSC);
                *(uint32_t*)&hs[HQ + (r+8)*72 + e] =
                    f2h2((qc[mi][ni][2] + bb.x) * QSC, (qc[mi][ni][3] + bb.y) * QSC);
            }
        }
    }
    // K0/V0 copy (HK0 now free)
#pragma unroll
    for (int i = 0; i < 2; i++) {
        int lin = tid + i * 256; int r = lin >> 3, ch = lin & 7;
        *(uint4*)&hs[HK0 + r*72 + ch*8] = *(const uint4*)(kg + r * 64 + ch * 8);
        *(uint4*)&hs[HV0 + r*72 + ch*8] = *(const uint4*)(vg + (size_t)r * SS + ch * 8);
    }
    __syncthreads();

    // preload Q fragments (loop-invariant)
    uint32_t qf[4][2][4];
#pragma unroll
    for (int kk = 0; kk < 4; kk++)
#pragma unroll
        for (int mi = 0; mi < 2; mi++)
            ldm_x4(qf[kk][mi], sb + (uint32_t)(HQ + (wm*32 + mi*16 + a_m)*72 + kk*16 + a_k)*2);

    float o[2][8][4] = {};
    float lacc[4] = {};

    for (int it = 0; it < NIT; it++) {
        int buf = it & 1;
        uint4 kr[2], vr[2];
        if (it + 1 < NIT) {
            const __half* kn = kg + (size_t)(it + 1) * 64 * DD;
            const __half* vn = vg + (size_t)(it + 1) * 64;
#pragma unroll
            for (int i = 0; i < 2; i++) {
                int lin = tid + i * 256; int r = lin >> 3, ch = lin & 7;
                kr[i] = *(const uint4*)(kn + r * 64 + ch * 8);
                vr[i] = *(const uint4*)(vn + (size_t)r * SS + ch * 8);
            }
        }
        uint32_t sK = sb + (uint32_t)(buf ? HK1 : HK0) * 2;
        uint32_t sV = sb + (uint32_t)(buf ? HV1 : HV0) * 2;

        // ---- S = Q @ K^T ----
        float s[2][4][4] = {};
#pragma unroll
        for (int kk = 0; kk < 4; kk++) {
            uint32_t kb0[4], kb1[4];
            ldm_x4(kb0, sK + (uint32_t)((wn*32      + b_n)*72 + kk*16 + b_k)*2);
            ldm_x4(kb1, sK + (uint32_t)((wn*32 + 16 + b_n)*72 + kk*16 + b_k)*2);
#pragma unroll
            for (int mi = 0; mi < 2; mi++) {
                mma16(s[mi][0], qf[kk][mi], kb0);
                mma16(s[mi][1], qf[kk][mi], kb0 + 2);
                mma16(s[mi][2], qf[kk][mi], kb1);
                mma16(s[mi][3], qf[kk][mi], kb1 + 2);
            }
        }
        // ---- exp (fp32 MUFU) interleaved with PV ----
#pragma unroll
        for (int kk = 0; kk < 2; kk++) {
            uint32_t a0[4], a1[4];
#pragma unroll
            for (int nj = 0; nj < 2; nj++) {
                int ni = 2*kk + nj;
                float p0 = ex2f(s[0][ni][0]), p1 = ex2f(s[0][ni][1]);
                float p2 = ex2f(s[0][ni][2]), p3 = ex2f(s[0][ni][3]);
                lacc[0] += p0 + p1;
                lacc[1] += p2 + p3;
                a0[2*nj  ] = f2h2(p0, p1);
                a0[2*nj+1] = f2h2(p2, p3);
                float q0 = ex2f(s[1][ni][0]), q1 = ex2f(s[1][ni][1]);
                float q2 = ex2f(s[1][ni][2]), q3 = ex2f(s[1][ni][3]);
                lacc[2] += q0 + q1;
                lacc[3] += q2 + q3;
                a1[2*nj  ] = f2h2(q0, q1);
                a1[2*nj+1] = f2h2(q2, q3);
            }
#pragma unroll
            for (int pr = 0; pr < 4; pr++) {
                uint32_t vb[4];
                ldm_x4(vb, sV + (uint32_t)((pr*16 + b_n)*72 + wn*32 + kk*16 + b_k)*2);
                mma16(o[0][2*pr  ], a0, vb);
                mma16(o[0][2*pr+1], a0, vb + 2);
                mma16(o[1][2*pr  ], a1, vb);
                mma16(o[1][2*pr+1], a1, vb + 2);
            }
        }
        if (it + 1 < NIT) {
            __half* kd = hs + (buf ? HK0 : HK1);
            __half* vd = hs + (buf ? HV0 : HV1);
#pragma unroll
            for (int i = 0; i < 2; i++) {
                int lin = tid + i * 256; int r = lin >> 3, ch = lin & 7;
                *(uint4*)&kd[r*72 + ch*8] = kr[i];
                *(uint4*)&vd[r*72 + ch*8] = vr[i];
            }
        }
        __syncthreads();
    }

    // ---- epilogue: combine kv-halves, divide by l, write FRAGMENT layout ----
#pragma unroll
    for (int i = 0; i < 4; i++) {
        lacc[i] += __shfl_xor_sync(0xffffffffu, lacc[i], 1);
        lacc[i] += __shfl_xor_sync(0xffffffffu, lacc[i], 2);
    }
    if (t == 0) {
#pragma unroll
        for (int mi = 0; mi < 2; mi++) {
            sf[FL + wn*128 + wm*32 + mi*16 + g    ] = lacc[mi*2];
            sf[FL + wn*128 + wm*32 + mi*16 + 8 + g] = lacc[mi*2 + 1];
        }
    }
    if (wn == 0) {
#pragma unroll
        for (int mi = 0; mi < 2; mi++)
#pragma unroll
        for (int ni = 0; ni < 8; ni++) {
            int r = wm*32 + mi*16 + g, c = ni*8 + 2*t;
            *(float2*)&sf[FST + r*68 + c]     = make_float2(o[mi][ni][0], o[mi][ni][1]);
            *(float2*)&sf[FST + (r+8)*68 + c] = make_float2(o[mi][ni][2], o[mi][ni][3]);
        }
    }
    __syncthreads();
    if (wn == 1) {
        uint4* gF = (uint4*)g_att;
        size_t trB = (size_t)((b * SS + qt * 128 + wm * 32) >> 4);   // + mi
#pragma unroll
        for (int mi = 0; mi < 2; mi++) {
            int rowA = wm*32 + mi*16 + g;
            float invA = 1.0f / (sf[FL + rowA]     + sf[FL + 128 + rowA]);
            float invB = 1.0f / (sf[FL + rowA + 8] + sf[FL + 128 + rowA + 8]);
            float fin[8][4];
#pragma unroll
            for (int ni = 0; ni < 8; ni++) {
                int c = ni*8 + 2*t;
                float2 pA = *(float2*)&sf[FST + rowA*68 + c];
                float2 pB = *(float2*)&sf[FST + (rowA+8)*68 + c];
                fin[ni][0] = (pA.x + o[mi][ni][0]) * invA;
                fin[ni][1] = (pA.y + o[mi][ni][1]) * invA;
                fin[ni][2] = (pB.x + o[mi][ni][2]) * invB;
                fin[ni][3] = (pB.y + o[mi][ni][3]) * invB;
            }
#pragma unroll
            for (int pr = 0; pr < 4; pr++) {
                uint4 u;
                u.x = f2h2(fin[2*pr  ][0], fin[2*pr  ][1]);
                u.y = f2h2(fin[2*pr  ][2], fin[2*pr  ][3]);
                u.z = f2h2(fin[2*pr+1][0], fin[2*pr+1][1]);
                u.w = f2h2(fin[2*pr+1][2], fin[2*pr+1][3]);
                gF[((trB + mi) * 64 + h*4 + pr) * 32 + lane] = u;
            }
        }
    }
}

// ======================= Kernel C: output projection (R11, measured best) =======================
// smem halves: Afrag[2][8192] | B[2][128][72]
#define PA0 0
#define PA1 8192
#define PB0 16384
#define PB1 25600
#define PSZ 69632

__global__ void __launch_bounds__(256, 2) proj_kernel(
    const float* __restrict__ bo, float* __restrict__ out)
{
    extern __shared__ __half hs[];
    int tid = threadIdx.x, lane = tid & 31, wid = tid >> 5;
    int g = lane >> 2, t = lane & 3;
    int l8 = lane & 7, qd = lane >> 3;
    int b_n = ((qd >> 1) << 3) + l8, b_k = (qd & 1) << 3;
    int wm = wid & 3, wn = wid >> 2;   // warp grid 4x2, warp tile 32m x 64n
    int e0 = blockIdx.x * 128, t0 = blockIdx.y * 128;
    const uint4* gA = (const uint4*)g_att;
    const __half* bg = g_wo + (size_t)e0 * EE;
    uint32_t sb = smem_u32(hs);
    int trB = t0 >> 4;

    // prologue: chunk 0 (A fragments + B tile) via cp.async
#pragma unroll
    for (int i = 0; i < 4; i++) {
        int idx = tid + i * 256;
        int rloc = idx >> 7, kloc = (idx >> 5) & 3, ll = idx & 31;
        cp16(sb + (uint32_t)idx * 16, &gA[((size_t)(trB + rloc) * 64 + kloc) * 32 + ll]);
    }
#pragma unroll
    for (int i = 0; i < 4; i++) {
        int lin = tid + i * 256; int r = lin >> 3, c8 = lin & 7;
        cp16(sb + (uint32_t)(PB0 + r*72 + c8*8)*2, bg + (size_t)r * EE + c8 * 8);
    }
    CPCOMMIT();

    float o[2][8][4] = {};

    for (int ch = 0; ch < 16; ch++) {
        int buf = ch & 1;
        if (ch + 1 < 16) {
            uint32_t dA = sb + (uint32_t)(buf ? PA0 : PA1) * 2;
            uint32_t dB = sb + (uint32_t)(buf ? PB0 : PB1) * 2;
#pragma unroll
            for (int i = 0; i < 4; i++) {
                int idx = tid + i * 256;
                int rloc = idx >> 7, kloc = (idx >> 5) & 3, ll = idx & 31;
                cp16(dA + (uint32_t)idx * 16,
                     &gA[((size_t)(trB + rloc) * 64 + (ch+1)*4 + kloc) * 32 + ll]);
            }
#pragma unroll
            for (int i = 0; i < 4; i++) {
                int lin = tid + i * 256; int r = lin >> 3, c8 = lin & 7;
                cp16(dB + (uint32_t)(r*72 + c8*8)*2, bg + (size_t)r * EE + (ch+1)*64 + c8 * 8);
            }
            CPCOMMIT();
            CPWAIT1();
        } else {
            CPWAIT0();
        }
        __syncthreads();

        const __half* As = hs + (buf ? PA1 : PA0);
        uint32_t sB = sb + (uint32_t)(buf ? PB1 : PB0) * 2;
#pragma unroll
        for (int kk = 0; kk < 4; kk++) {
            uint32_t a[2][4];
#pragma unroll
            for (int mi = 0; mi < 2; mi++) {
                uint4 u = *(const uint4*)&As[(((wm*2 + mi)*4 + kk)*32 + lane) * 8];
                a[mi][0] = u.x; a[mi][1] = u.y; a[mi][2] = u.z; a[mi][3] = u.w;
            }
#pragma unroll
            for (int pr = 0; pr < 4; pr++) {
                uint32_t bf[4];
                ldm_x4(bf, sB + (uint32_t)((wn*64 + pr*16 + b_n)*72 + kk*16 + b_k)*2);
                mma16(o[0][2*pr  ], a[0], bf);
                mma16(o[0][2*pr+1], a[0], bf + 2);
                mma16(o[1][2*pr  ], a[1], bf);
                mma16(o[1][2*pr+1], a[1], bf + 2);
            }
        }
        __syncthreads();
    }

    // epilogue: direct STG with bias
#pragma unroll
    for (int mi = 0; mi < 2; mi++) {
        int rA = t0 + wm*32 + mi*16 + g;
#pragma unroll
        for (int ni = 0; ni < 8; ni++) {
            int e = e0 + wn*64 + ni*8 + 2*t;
            float2 bb = *(const float2*)(bo + e);
            *(float2*)&out[(size_t)rA * EE + e] =
                make_float2(o[mi][ni][0] + bb.x, o[mi][ni][1] + bb.y);
            *(float2*)&out[(size_t)(rA + 8) * EE + e] =
                make_float2(o[mi][ni][2] + bb.x, o[mi][ni][3] + bb.y);
        }
    }
}

// ======================= launch =======================
extern "C" void kernel_launch(void* const* d_in, const int* in_sizes, int n_in,
                              void* d_out, int out_size) {
    const float* x  = (const float*)d_in[0];
    const float* Wq = (const float*)d_in[1];
    const float* Wk = (const float*)d_in[2];
    const float* Wv = (const float*)d_in[3];
    const float* bq = (const float*)d_in[4];
    const float* bk = (const float*)d_in[5];
    const float* bv = (const float*)d_in[6];
    const float* Wo = (const float*)d_in[7];
    const float* bo = (const float*)d_in[8];
    float* out = (float*)d_out;

    cudaFuncSetAttribute(kv_kernel,   cudaFuncAttributeMaxDynamicSharedMemorySize, QK_SZ);
    cudaFuncSetAttribute(attn_kernel, cudaFuncAttributeMaxDynamicSharedMemorySize, ASZ);
    cudaFuncSetAttribute(proj_kernel, cudaFuncAttributeMaxDynamicSharedMemorySize, PSZ);

    conv_wo<<<EE * EE / 1024, 256>>>(Wo);
    kv_kernel<<<dim3(BB * SS / 128, HH / 2), 256, QK_SZ>>>(x, Wk, Wv, bk, bv);
    attn_kernel<<<dim3(SS / 128, HH, BB), 256, ASZ>>>(x, Wq, bq);
    proj_kernel<<<dim3(EE / 128, BB * SS / 128), 256, PSZ>>>(bo, out);
}

// round 17
// speedup vs baseline: 1.1597x; 1.1597x over previous
#include <cuda_runtime.h>
#include <cuda_fp16.h>
#include <cstdint>

#define BB 4
#define SS 2048
#define EE 1024
#define HH 16
#define DD 64
#define QSC 0.18033688011112042f   // 0.125 * log2(e), folded into Q

// Scratch (fp16)
__device__ __half g_q[(size_t)BB*HH*SS*DD];    // [B][H][S][D] (pre-scaled by QSC)
__device__ __half g_k[(size_t)BB*HH*SS*DD];    // [B][H][S][D]
__device__ __half g_vT[(size_t)BB*HH*DD*SS];   // [B][H][D][S] (pre-transposed)
__device__ __half g_att[(size_t)BB*SS*EE];     // FRAGMENT layout: uint4[tile_r][tile_k][lane]
__device__ __half g_wo[(size_t)EE*EE];         // fp16 copy of Wo

#define H2U(x) (*(const uint32_t*)&(x))

__device__ __forceinline__ uint32_t f2h2(float a, float b) {
    __half2 h = __floats2half2_rn(a, b);
    return H2U(h);
}
__device__ __forceinline__ float ex2f(float x) {   // single MUFU op
    float r;
    asm("ex2.approx.f32 %0, %1;" : "=f"(r) : "f"(x));
    return r;
}
__device__ __forceinline__ uint32_t smem_u32(const void* p) {
    return (uint32_t)__cvta_generic_to_shared(p);
}
__device__ __forceinline__ void ldm_x4(uint32_t* r, uint32_t a) {
    asm volatile("ldmatrix.sync.aligned.m8n8.x4.shared.b16 {%0,%1,%2,%3}, [%4];"
        : "=r"(r[0]), "=r"(r[1]), "=r"(r[2]), "=r"(r[3]) : "r"(a));
}
__device__ __forceinline__ void cp16(uint32_t dst, const void* src) {
    asm volatile("cp.async.cg.shared.global [%0], [%1], 16;" :: "r"(dst), "l"(src));
}
#define CPCOMMIT() asm volatile("cp.async.commit_group;" ::: "memory")
#define CPWAIT0()  asm volatile("cp.async.wait_group 0;" ::: "memory")
#define CPWAIT1()  asm volatile("cp.async.wait_group 1;" ::: "memory")

// D += A(m16k16 row) * B(n8k16 col), fp16 in / fp32 acc
__device__ __forceinline__ void mma16(float c[4], const uint32_t a[4], const uint32_t b[2]) {
    asm volatile("mma.sync.aligned.m16n8k16.row.col.f32.f16.f16.f32 "
        "{%0,%1,%2,%3}, {%4,%5,%6,%7}, {%8,%9}, {%0,%1,%2,%3};"
        : "+f"(c[0]), "+f"(c[1]), "+f"(c[2]), "+f"(c[3])
        : "r"(a[0]), "r"(a[1]), "r"(a[2]), "r"(a[3]), "r"(b[0]), "r"(b[1]));
}

// ======================= Kernel 0: Wo -> fp16 =======================
__global__ void __launch_bounds__(256) conv_wo(const float* __restrict__ Wo) {
    int i = (blockIdx.x * 256 + threadIdx.x) * 4;
    float4 v = *(const float4*)(Wo + i);
    *(uint2*)&g_wo[i] = make_uint2(f2h2(v.x, v.y), f2h2(v.z, v.w));
}

// ======================= Kernel A: QKV projections, 1 head/CTA, 2 CTAs/SM =======================
// smem halves: X[128][72] | W[3][64][72]
#define HX 0
#define HW 9216
#define QK_SZ ((9216 + 3*4608) * 2)   // 46080 bytes

__global__ void __launch_bounds__(256, 2) qkv_kernel(
    const float* __restrict__ x,
    const float* __restrict__ Wq, const float* __restrict__ Wk, const float* __restrict__ Wv,
    const float* __restrict__ bq, const float* __restrict__ bk, const float* __restrict__ bv)
{
    extern __shared__ __half hs[];
    int tid = threadIdx.x, lane = tid & 31, wid = tid >> 5;
    int g = lane >> 2, t = lane & 3;
    int l8 = lane & 7, qd = lane >> 3;
    int a_m = ((qd & 1) << 3) + l8, a_k = (qd >> 1) << 3;
    int b_n = ((qd >> 1) << 3) + l8, b_k = (qd & 1) << 3;
    int wm = wid & 3, wn = wid >> 2;
    int h = blockIdx.y;
    int t0 = blockIdx.x * 128;
    int b = t0 >> 11, s0 = t0 & (SS - 1);
    uint32_t sb = smem_u32(hs);

    // stage X slice for this head
#pragma unroll
    for (int i = 0; i < 8; i++) {
        int lin = tid + i * 256; int r = lin >> 4, c = (lin & 15) << 2;
        float4 v = *(const float4*)(x + (size_t)(t0 + r) * EE + h * DD + c);
        *(uint2*)&hs[HX + r*72 + c] = make_uint2(f2h2(v.x, v.y), f2h2(v.z, v.w));
    }
    // stage Wq/Wk/Wv col-major [e][d]
    const float* Wg[3] = {Wq + (size_t)h*DD*DD, Wk + (size_t)h*DD*DD, Wv + (size_t)h*DD*DD};
#pragma unroll
    for (int w = 0; w < 3; w++) {
        __half* Wd = hs + HW + w * 4608;
#pragma unroll
        for (int i = 0; i < 4; i++) {
            int lin = tid + i * 256; int d = lin >> 4, e = (lin & 15) << 2;
            float4 v = *(const float4*)(Wg[w] + d * DD + e);
            Wd[(e+0)*72 + d] = __float2half_rn(v.x);
            Wd[(e+1)*72 + d] = __float2half_rn(v.y);
            Wd[(e+2)*72 + d] = __float2half_rn(v.z);
            Wd[(e+3)*72 + d] = __float2half_rn(v.w);
        }
    }
    __syncthreads();

    // preload X fragments once (32 regs)
    uint32_t af[4][2][4];
#pragma unroll
    for (int kk = 0; kk < 4; kk++)
#pragma unroll
        for (int mi = 0; mi < 2; mi++)
            ldm_x4(af[kk][mi], sb + (uint32_t)(HX + (wm*32 + mi*16 + a_m)*72 + kk*16 + a_k)*2);

    size_t base  = (size_t)(b * HH + h) * SS * DD;
    size_t vbase = (size_t)(b * HH + h) * DD * SS;

    // ---- Q (scoped accumulators; reg reuse across projections) ----
    {
        float c[2][4][4] = {};
#pragma unroll
        for (int kk = 0; kk < 4; kk++)
#pragma unroll
            for (int pr = 0; pr < 2; pr++) {
                uint32_t bf[4];
                ldm_x4(bf, sb + (uint32_t)(HW + (wn*32 + pr*16 + b_n)*72 + kk*16 + b_k)*2);
                mma16(c[0][2*pr  ], af[kk][0], bf);
                mma16(c[0][2*pr+1], af[kk][0], bf + 2);
                mma16(c[1][2*pr  ], af[kk][1], bf);
                mma16(c[1][2*pr+1], af[kk][1], bf + 2);
            }
#pragma unroll
        for (int ni = 0; ni < 4; ni++) {
            int e = wn*32 + ni*8 + 2*t;
            float2 bb2 = *(const float2*)(bq + h*DD + e);
#pragma unroll
            for (int mi = 0; mi < 2; mi++) {
                int r = wm*32 + mi*16 + g;
                *(uint32_t*)(g_q + base + (size_t)(s0 + r    )*DD + e) =
                    f2h2((c[mi][ni][0] + bb2.x) * QSC, (c[mi][ni][1] + bb2.y) * QSC);
                *(uint32_t*)(g_q + base + (size_t)(s0 + r + 8)*DD + e) =
                    f2h2((c[mi][ni][2] + bb2.x) * QSC, (c[mi][ni][3] + bb2.y) * QSC);
            }
        }
    }
    // ---- K ----
    {
        float c[2][4][4] = {};
#pragma unroll
        for (int kk = 0; kk < 4; kk++)
#pragma unroll
            for (int pr = 0; pr < 2; pr++) {
                uint32_t bf[4];
                ldm_x4(bf, sb + (uint32_t)(HW + 4608 + (wn*32 + pr*16 + b_n)*72 + kk*16 + b_k)*2);
                mma16(c[0][2*pr  ], af[kk][0], bf);
                mma16(c[0][2*pr+1], af[kk][0], bf + 2);
                mma16(c[1][2*pr  ], af[kk][1], bf);
                mma16(c[1][2*pr+1], af[kk][1], bf + 2);
            }
#pragma unroll
        for (int ni = 0; ni < 4; ni++) {
            int e = wn*32 + ni*8 + 2*t;
            float2 bb2 = *(const float2*)(bk + h*DD + e);
#pragma unroll
            for (int mi = 0; mi < 2; mi++) {
                int r = wm*32 + mi*16 + g;
                *(uint32_t*)(g_k + base + (size_t)(s0 + r    )*DD + e) =
                    f2h2(c[mi][ni][0] + bb2.x, c[mi][ni][1] + bb2.y);
                *(uint32_t*)(g_k + base + (size_t)(s0 + r + 8)*DD + e) =
                    f2h2(c[mi][ni][2] + bb2.x, c[mi][ni][3] + bb2.y);
            }
        }
    }
    // ---- V (stored transposed [d][s]) ----
    {
        float c[2][4][4] = {};
#pragma unroll
        for (int kk = 0; kk < 4; kk++)
#pragma unroll
            for (int pr = 0; pr < 2; pr++) {
                uint32_t bf[4];
                ldm_x4(bf, sb + (uint32_t)(HW + 9216 + (wn*32 + pr*16 + b_n)*72 + kk*16 + b_k)*2);
                mma16(c[0][2*pr  ], af[kk][0], bf);
                mma16(c[0][2*pr+1], af[kk][0], bf + 2);
                mma16(c[1][2*pr  ], af[kk][1], bf);
                mma16(c[1][2*pr+1], af[kk][1], bf + 2);
            }
#pragma unroll
        for (int ni = 0; ni < 4; ni++) {
            int e = wn*32 + ni*8 + 2*t;
            float2 bb2 = *(const float2*)(bv + h*DD + e);
#pragma unroll
            for (int mi = 0; mi < 2; mi++) {
                int r = wm*32 + mi*16 + g;
                g_vT[vbase + (size_t)(e  )*SS + s0 + r    ] = __float2half_rn(c[mi][ni][0] + bb2.x);
                g_vT[vbase + (size_t)(e+1)*SS + s0 + r    ] = __float2half_rn(c[mi][ni][1] + bb2.y);
                g_vT[vbase + (size_t)(e  )*SS + s0 + r + 8] = __float2half_rn(c[mi][ni][2] + bb2.x);
                g_vT[vbase + (size_t)(e+1)*SS + s0 + r + 8] = __float2half_rn(c[mi][ni][3] + bb2.y);
            }
        }
    }
}

// ======================= Kernel B: flash attention (R11, measured best — FROZEN) =======================
#define HQ  0
#define HK0 9216
#define HK1 13824
#define HV0 18432
#define HV1 23040
#define FST 13824              // float index of stage
#define FL  22528              // float index of l[2][128]
#define ASZ ((22528 + 256) * 4)
#define NIT (SS/64)

__global__ void __launch_bounds__(256, 1) attn_kernel() {
    extern __shared__ __half hs[];
    float* sf = (float*)hs;
    int tid = threadIdx.x, lane = tid & 31, wid = tid >> 5;
    int g = lane >> 2, t = lane & 3;
    int l8 = lane & 7, qd = lane >> 3;
    int a_m = ((qd & 1) << 3) + l8, a_k = (qd >> 1) << 3;
    int b_n = ((qd >> 1) << 3) + l8, b_k = (qd & 1) << 3;
    int wm = wid & 3, wn = wid >> 2;
    int qt = blockIdx.x, h = blockIdx.y, b = blockIdx.z;
    size_t bh  = (size_t)(b * HH + h) * SS * DD;
    size_t bhv = (size_t)(b * HH + h) * DD * SS;
    const __half* qg = g_q + bh + (size_t)qt * 128 * DD;
    const __half* kg = g_k + bh;
    const __half* vg = g_vT + bhv;
    uint32_t sb = smem_u32(hs);

    // prologue: Q copy (already scaled), K0/V0 copy
#pragma unroll
    for (int i = 0; i < 4; i++) {
        int lin = tid + i * 256; int r = lin >> 3, ch = lin & 7;
        *(uint4*)&hs[HQ + r*72 + ch*8] = *(const uint4*)(qg + r * 64 + ch * 8);
    }
#pragma unroll
    for (int i = 0; i < 2; i++) {
        int lin = tid + i * 256; int r = lin >> 3, ch = lin & 7;
        *(uint4*)&hs[HK0 + r*72 + ch*8] = *(const uint4*)(kg + r * 64 + ch * 8);
        *(uint4*)&hs[HV0 + r*72 + ch*8] = *(const uint4*)(vg + (size_t)r * SS + ch * 8);
    }
    __syncthreads();

    // preload Q fragments (loop-invariant)
    uint32_t qf[4][2][4];
#pragma unroll
    for (int kk = 0; kk < 4; kk++)
#pragma unroll
        for (int mi = 0; mi < 2; mi++)
            ldm_x4(qf[kk][mi], sb + (uint32_t)(HQ + (wm*32 + mi*16 + a_m)*72 + kk*16 + a_k)*2);

    float o[2][8][4] = {};
    float lacc[4] = {};

    for (int it = 0; it < NIT; it++) {
        int buf = it & 1;
        uint4 kr[2], vr[2];
        if (it + 1 < NIT) {
            const __half* kn = kg + (size_t)(it + 1) * 64 * DD;
            const __half* vn = vg + (size_t)(it + 1) * 64;
#pragma unroll
            for (int i = 0; i < 2; i++) {
                int lin = tid + i * 256; int r = lin >> 3, ch = lin & 7;
                kr[i] = *(const uint4*)(kn + r * 64 + ch * 8);
                vr[i] = *(const uint4*)(vn + (size_t)r * SS + ch * 8);
            }
        }
        uint32_t sK = sb + (uint32_t)(buf ? HK1 : HK0) * 2;
        uint32_t sV = sb + (uint32_t)(buf ? HV1 : HV0) * 2;

        // ---- S = Q @ K^T ----
        float s[2][4][4] = {};
#pragma unroll
        for (int kk = 0; kk < 4; kk++) {
            uint32_t kb0[4], kb1[4];
            ldm_x4(kb0, sK + (uint32_t)((wn*32      + b_n)*72 + kk*16 + b_k)*2);
            ldm_x4(kb1, sK + (uint32_t)((wn*32 + 16 + b_n)*72 + kk*16 + b_k)*2);
#pragma unroll
            for (int mi = 0; mi < 2; mi++) {
                mma16(s[mi][0], qf[kk][mi], kb0);
                mma16(s[mi][1], qf[kk][mi], kb0 + 2);
                mma16(s[mi][2], qf[kk][mi], kb1);
                mma16(s[mi][3], qf[kk][mi], kb1 + 2);
            }
        }
        // ---- exp (fp32 MUFU) interleaved with PV ----
#pragma unroll
        for (int kk = 0; kk < 2; kk++) {
            uint32_t a0[4], a1[4];
#pragma unroll
            for (int nj = 0; nj < 2; nj++) {
                int ni = 2*kk + nj;
                float p0 = ex2f(s[0][ni][0]), p1 = ex2f(s[0][ni][1]);
                float p2 = ex2f(s[0][ni][2]), p3 = ex2f(s[0][ni][3]);
                lacc[0] += p0 + p1;
                lacc[1] += p2 + p3;
                a0[2*nj  ] = f2h2(p0, p1);
                a0[2*nj+1] = f2h2(p2, p3);
                float q0 = ex2f(s[1][ni][0]), q1 = ex2f(s[1][ni][1]);
                float q2 = ex2f(s[1][ni][2]), q3 = ex2f(s[1][ni][3]);
                lacc[2] += q0 + q1;
                lacc[3] += q2 + q3;
                a1[2*nj  ] = f2h2(q0, q1);
                a1[2*nj+1] = f2h2(q2, q3);
            }
#pragma unroll
            for (int pr = 0; pr < 4; pr++) {
                uint32_t vb[4];
                ldm_x4(vb, sV + (uint32_t)((pr*16 + b_n)*72 + wn*32 + kk*16 + b_k)*2);
                mma16(o[0][2*pr  ], a0, vb);
                mma16(o[0][2*pr+1], a0, vb + 2);
                mma16(o[1][2*pr  ], a1, vb);
                mma16(o[1][2*pr+1], a1, vb + 2);
            }
        }
        if (it + 1 < NIT) {
            __half* kd = hs + (buf ? HK0 : HK1);
            __half* vd = hs + (buf ? HV0 : HV1);
#pragma unroll
            for (int i = 0; i < 2; i++) {
                int lin = tid + i * 256; int r = lin >> 3, ch = lin & 7;
                *(uint4*)&kd[r*72 + ch*8] = kr[i];
                *(uint4*)&vd[r*72 + ch*8] = vr[i];
            }
        }
        __syncthreads();
    }

    // ---- epilogue: combine kv-halves, divide by l, write FRAGMENT layout ----
#pragma unroll
    for (int i = 0; i < 4; i++) {
        lacc[i] += __shfl_xor_sync(0xffffffffu, lacc[i], 1);
        lacc[i] += __shfl_xor_sync(0xffffffffu, lacc[i], 2);
    }
    if (t == 0) {
#pragma unroll
        for (int mi = 0; mi < 2; mi++) {
            sf[FL + wn*128 + wm*32 + mi*16 + g    ] = lacc[mi*2];
            sf[FL + wn*128 + wm*32 + mi*16 + 8 + g] = lacc[mi*2 + 1];
        }
    }
    if (wn == 0) {
#pragma unroll
        for (int mi = 0; mi < 2; mi++)
#pragma unroll
        for (int ni = 0; ni < 8; ni++) {
            int r = wm*32 + mi*16 + g, c = ni*8 + 2*t;
            *(float2*)&sf[FST + r*68 + c]     = make_float2(o[mi][ni][0], o[mi][ni][1]);
            *(float2*)&sf[FST + (r+8)*68 + c] = make_float2(o[mi][ni][2], o[mi][ni][3]);
        }
    }
    __syncthreads();
    if (wn == 1) {
        uint4* gF = (uint4*)g_att;
        size_t trB = (size_t)((b * SS + qt * 128 + wm * 32) >> 4);   // + mi
#pragma unroll
        for (int mi = 0; mi < 2; mi++) {
            int rowA = wm*32 + mi*16 + g;
            float invA = 1.0f / (sf[FL + rowA]     + sf[FL + 128 + rowA]);
            float invB = 1.0f / (sf[FL + rowA + 8] + sf[FL + 128 + rowA + 8]);
            float fin[8][4];
#pragma unroll
            for (int ni = 0; ni < 8; ni++) {
                int c = ni*8 + 2*t;
                float2 pA = *(float2*)&sf[FST + rowA*68 + c];
                float2 pB = *(float2*)&sf[FST + (rowA+8)*68 + c];
                fin[ni][0] = (pA.x + o[mi][ni][0]) * invA;
                fin[ni][1] = (pA.y + o[mi][ni][1]) * invA;
                fin[ni][2] = (pB.x + o[mi][ni][2]) * invB;
                fin[ni][3] = (pB.y + o[mi][ni][3]) * invB;
            }
#pragma unroll
            for (int pr = 0; pr < 4; pr++) {
                uint4 u;
                u.x = f2h2(fin[2*pr  ][0], fin[2*pr  ][1]);
                u.y = f2h2(fin[2*pr  ][2], fin[2*pr  ][3]);
                u.z = f2h2(fin[2*pr+1][0], fin[2*pr+1][1]);
                u.w = f2h2(fin[2*pr+1][2], fin[2*pr+1][3]);
                gF[((trB + mi) * 64 + h*4 + pr) * 32 + lane] = u;
            }
        }
    }
}

// ======================= Kernel C: output projection (R11, measured best — FROZEN) =======================
// smem halves: Afrag[2][8192] | B[2][128][72]
#define PA0 0
#define PA1 8192
#define PB0 16384
#define PB1 25600
#define PSZ 69632

__global__ void __launch_bounds__(256, 2) proj_kernel(
    const float* __restrict__ bo, float* __restrict__ out)
{
    extern __shared__ __half hs[];
    int tid = threadIdx.x, lane = tid & 31, wid = tid >> 5;
    int g = lane >> 2, t = lane & 3;
    int l8 = lane & 7, qd = lane >> 3;
    int b_n = ((qd >> 1) << 3) + l8, b_k = (qd & 1) << 3;
    int wm = wid & 3, wn = wid >> 2;   // warp grid 4x2, warp tile 32m x 64n
    int e0 = blockIdx.x * 128, t0 = blockIdx.y * 128;
    const uint4* gA = (const uint4*)g_att;
    const __half* bg = g_wo + (size_t)e0 * EE;
    uint32_t sb = smem_u32(hs);
    int trB = t0 >> 4;

    // prologue: chunk 0 (A fragments + B tile) via cp.async
#pragma unroll
    for (int i = 0; i < 4; i++) {
        int idx = tid + i * 256;
        int rloc = idx >> 7, kloc = (idx >> 5) & 3, ll = idx & 31;
        cp16(sb + (uint32_t)idx * 16, &gA[((size_t)(trB + rloc) * 64 + kloc) * 32 + ll]);
    }
#pragma unroll
    for (int i = 0; i < 4; i++) {
        int lin = tid + i * 256; int r = lin >> 3, c8 = lin & 7;
        cp16(sb + (uint32_t)(PB0 + r*72 + c8*8)*2, bg + (size_t)r * EE + c8 * 8);
    }
    CPCOMMIT();

    float o[2][8][4] = {};

    for (int ch = 0; ch < 16; ch++) {
        int buf = ch & 1;
        if (ch + 1 < 16) {
            uint32_t dA = sb + (uint32_t)(buf ? PA0 : PA1) * 2;
            uint32_t dB = sb + (uint32_t)(buf ? PB0 : PB1) * 2;
#pragma unroll
            for (int i = 0; i < 4; i++) {
                int idx = tid + i * 256;
                int rloc = idx >> 7, kloc = (idx >> 5) & 3, ll = idx & 31;
                cp16(dA + (uint32_t)idx * 16,
                     &gA[((size_t)(trB + rloc) * 64 + (ch+1)*4 + kloc) * 32 + ll]);
            }
#pragma unroll
            for (int i = 0; i < 4; i++) {
                int lin = tid + i * 256; int r = lin >> 3, c8 = lin & 7;
                cp16(dB + (uint32_t)(r*72 + c8*8)*2, bg + (size_t)r * EE + (ch+1)*64 + c8 * 8);
            }
            CPCOMMIT();
            CPWAIT1();
        } else {
            CPWAIT0();
        }
        __syncthreads();

        const __half* As = hs + (buf ? PA1 : PA0);
        uint32_t sB = sb + (uint32_t)(buf ? PB1 : PB0) * 2;
#pragma unroll
        for (int kk = 0; kk < 4; kk++) {
            uint32_t a[2][4];
#pragma unroll
            for (int mi = 0; mi < 2; mi++) {
                uint4 u = *(const uint4*)&As[(((wm*2 + mi)*4 + kk)*32 + lane) * 8];
                a[mi][0] = u.x; a[mi][1] = u.y; a[mi][2] = u.z; a[mi][3] = u.w;
            }
#pragma unroll
            for (int pr = 0; pr < 4; pr++) {
                uint32_t bf[4];
                ldm_x4(bf, sB + (uint32_t)((wn*64 + pr*16 + b_n)*72 + kk*16 + b_k)*2);
                mma16(o[0][2*pr  ], a[0], bf);
                mma16(o[0][2*pr+1], a[0], bf + 2);
                mma16(o[1][2*pr  ], a[1], bf);
                mma16(o[1][2*pr+1], a[1], bf + 2);
            }
        }
        __syncthreads();
    }

    // epilogue: direct STG with bias
#pragma unroll
    for (int mi = 0; mi < 2; mi++) {
        int rA = t0 + wm*32 + mi*16 + g;
#pragma unroll
        for (int ni = 0; ni < 8; ni++) {
            int e = e0 + wn*64 + ni*8 + 2*t;
            float2 bb = *(const float2*)(bo + e);
            *(float2*)&out[(size_t)rA * EE + e] =
                make_float2(o[mi][ni][0] + bb.x, o[mi][ni][1] + bb.y);
            *(float2*)&out[(size_t)(rA + 8) * EE + e] =
                make_float2(o[mi][ni][2] + bb.x, o[mi][ni][3] + bb.y);
        }
    }
}

// ======================= launch =======================
extern "C" void kernel_launch(void* const* d_in, const int* in_sizes, int n_in,
                              void* d_out, int out_size) {
    const float* x  = (const float*)d_in[0];
    const float* Wq = (const float*)d_in[1];
    const float* Wk = (const float*)d_in[2];
    const float* Wv = (const float*)d_in[3];
    const float* bq = (const float*)d_in[4];
    const float* bk = (const float*)d_in[5];
    const float* bv = (const float*)d_in[6];
    const float* Wo = (const float*)d_in[7];
    const float* bo = (const float*)d_in[8];
    float* out = (float*)d_out;

    cudaFuncSetAttribute(qkv_kernel,  cudaFuncAttributeMaxDynamicSharedMemorySize, QK_SZ);
    cudaFuncSetAttribute(attn_kernel, cudaFuncAttributeMaxDynamicSharedMemorySize, ASZ);
    cudaFuncSetAttribute(proj_kernel, cudaFuncAttributeMaxDynamicSharedMemorySize, PSZ);

    conv_wo<<<EE * EE / 1024, 256>>>(Wo);
    qkv_kernel<<<dim3(BB * SS / 128, HH), 256, QK_SZ>>>(x, Wq, Wk, Wv, bq, bk, bv);
    attn_kernel<<<dim3(SS / 128, HH, BB), 256, ASZ>>>();
    proj_kernel<<<dim3(EE / 128, BB * SS / 128), 256, PSZ>>>(bo, out);
}